// round 4
// baseline (speedup 1.0000x reference)
#include <cuda_runtime.h>

typedef unsigned long long u64;
#define N_NODES 50000
#define N_EDGES 800000
#define DIM 128
#define KPI 0.62831853071795865f
#define FULL 0xffffffffu

// ---- f32x2 helpers (PTX-only FFMA2 path) ----
__device__ __forceinline__ u64 pk2(float lo, float hi) {
    u64 r; asm("mov.b64 %0,{%1,%2};" : "=l"(r) : "r"(__float_as_uint(lo)), "r"(__float_as_uint(hi))); return r;
}
__device__ __forceinline__ void upk2(u64 v, float& lo, float& hi) {
    unsigned a, b; asm("mov.b64 {%0,%1},%2;" : "=r"(a), "=r"(b) : "l"(v));
    lo = __uint_as_float(a); hi = __uint_as_float(b);
}
__device__ __forceinline__ u64 fma2(u64 a, u64 b, u64 c) {
    u64 d; asm("fma.rn.f32x2 %0,%1,%2,%3;" : "=l"(d) : "l"(a), "l"(b), "l"(c)); return d;
}
__device__ __forceinline__ u64 mul2(u64 a, u64 b) {
    u64 d; asm("mul.rn.f32x2 %0,%1,%2;" : "=l"(d) : "l"(a), "l"(b)); return d;
}
__device__ __forceinline__ u64 add2(u64 a, u64 b) {
    u64 d; asm("add.rn.f32x2 %0,%1,%2;" : "=l"(d) : "l"(a), "l"(b)); return d;
}

// ---- scratch ----
__device__ float2 g_P2[(size_t)N_NODES * 512];  // [n][hp][dim] -> (P[2hp][d],P[2hp+1][d])*0.25
__device__ float  g_c[N_NODES * 8];             // (q.b_K)*0.25
__device__ float  g_WKT[DIM * DIM];
__device__ int    g_counts[N_NODES];
__device__ int    g_offsets[N_NODES + 1];
__device__ int    g_cursor[N_NODES];
__device__ int2   g_pe[N_EDGES];                // (edge, phi bits), CSR order

// ---- CSR build ----
__global__ void k_zero() {
    int i = blockIdx.x * blockDim.x + threadIdx.x;
    if (i < N_NODES) g_counts[i] = 0;
}
__global__ void k_hist(const int* __restrict__ ei) {
    int e = blockIdx.x * blockDim.x + threadIdx.x;
    if (e < N_EDGES) atomicAdd(&g_counts[ei[N_EDGES + e]], 1);
}
__global__ void k_scan() {
    __shared__ int wsum[32];
    int t = threadIdx.x, lane = t & 31, wid = t >> 5;
    int carry = 0;
    for (int base = 0; base < N_NODES; base += 1024) {
        int i = base + t;
        int v = (i < N_NODES) ? g_counts[i] : 0;
        int x = v;
        #pragma unroll
        for (int o = 1; o < 32; o <<= 1) { int y = __shfl_up_sync(FULL, x, o); if (lane >= o) x += y; }
        if (lane == 31) wsum[wid] = x;
        __syncthreads();
        if (wid == 0) {
            int s = wsum[lane];
            #pragma unroll
            for (int o = 1; o < 32; o <<= 1) { int y = __shfl_up_sync(FULL, s, o); if (lane >= o) s += y; }
            wsum[lane] = s;
        }
        __syncthreads();
        int excl = x - v + (wid ? wsum[wid - 1] : 0);
        if (i < N_NODES) { g_offsets[i] = carry + excl; g_cursor[i] = carry + excl; }
        carry += wsum[31];
        __syncthreads();
    }
    if (t == 0) g_offsets[N_NODES] = carry;
}
__global__ void k_scatter(const int* __restrict__ ei, const float* __restrict__ elen) {
    int e = blockIdx.x * blockDim.x + threadIdx.x;
    if (e < N_EDGES) {
        int j = ei[N_EDGES + e];
        int pos = atomicAdd(&g_cursor[j], 1);
        float phi = fmaf(0.5f, __cosf(elen[e] * KPI), 0.5f);
        g_pe[pos] = make_int2(e, __float_as_int(phi));
    }
}
__global__ void k_wkt(const float* __restrict__ WK) {
    int i = blockIdx.x * blockDim.x + threadIdx.x;
    if (i < DIM * DIM) g_WKT[(i % DIM) * DIM + (i / DIM)] = WK[i];
}

// ---- node precompute: q = xW_Q+b_Q; P[h] = W_K[:,h]q_h (f32x2 column pairs) ----
__global__ void __launch_bounds__(64) k_qp(
    const float* __restrict__ x, const float* __restrict__ WQ,
    const float* __restrict__ bQ, const float* __restrict__ bK)
{
    __shared__ u64 sx2[DIM], sq2[DIM];
    __shared__ float sqs[DIM];
    int n = blockIdx.x, t = threadIdx.x, c = 2 * t;
    {
        float v0 = x[n * DIM + t], v1 = x[n * DIM + t + 64];
        sx2[t] = pk2(v0, v0); sx2[t + 64] = pk2(v1, v1);
    }
    __syncthreads();
    const u64* wq = reinterpret_cast<const u64*>(WQ);
    u64 q2 = pk2(bQ[c], bQ[c + 1]);
    #pragma unroll 8
    for (int s = 0; s < DIM; s++) q2 = fma2(sx2[s], wq[s * 64 + t], q2);
    float q0, q1; upk2(q2, q0, q1);
    sq2[c] = pk2(q0, q0); sq2[c + 1] = pk2(q1, q1);
    sqs[c] = q0; sqs[c + 1] = q1;
    __syncthreads();
    const u64* wk = reinterpret_cast<const u64*>(g_WKT);
    float pc[8], pd[8];
    #pragma unroll
    for (int h = 0; h < 8; h++) {
        u64 a2 = 0ull;
        #pragma unroll
        for (int k = 0; k < 16; k++) a2 = fma2(sq2[h * 16 + k], wk[(h * 16 + k) * 64 + t], a2);
        upk2(a2, pc[h], pd[h]);
    }
    float2* gp = g_P2 + (size_t)n * 512;
    #pragma unroll
    for (int hp = 0; hp < 4; hp++) {
        gp[hp * 128 + c]     = make_float2(0.25f * pc[2 * hp], 0.25f * pc[2 * hp + 1]);
        gp[hp * 128 + c + 1] = make_float2(0.25f * pd[2 * hp], 0.25f * pd[2 * hp + 1]);
    }
    if (t < 8) {
        float cc = 0.f;
        #pragma unroll
        for (int k = 0; k < 16; k++) cc = fmaf(sqs[t * 16 + k], bK[t * 16 + k], cc);
        g_c[n * 8 + t] = cc * 0.25f;
    }
}

// ---- fused edge pass + block-cooperative epilogue; warp = node, 8 nodes/block ----
__global__ void __launch_bounds__(256, 2) k_edge(
    const float4* __restrict__ ea4,
    const float* __restrict__ WV, const float* __restrict__ bV,
    const float* __restrict__ WO, const float* __restrict__ bO,
    float* __restrict__ out)
{
    __shared__ float2 sUP[4][8][DIM];   // [node-pair][head][dim] = (Unorm[2np], Unorm[2np+1])
    __shared__ float  sT[8][8];         // [node_local][head] = sum(alpha*phi)
    __shared__ float2 sNOP[4][DIM];     // node_out pairs
    int tid = threadIdx.x, w = tid >> 5, l = tid & 31;
    int n = blockIdx.x * 8 + w;

    u64 P2[4][4];
    {
        const u64* gp = reinterpret_cast<const u64*>(g_P2) + (size_t)n * 512;
        #pragma unroll
        for (int hp = 0; hp < 4; hp++)
            #pragma unroll
            for (int dd = 0; dd < 4; dd++) P2[hp][dd] = gp[hp * 128 + 4 * l + dd];
    }
    float ch = g_c[n * 8 + (l >> 2)];
    u64 U2[4][4];
    #pragma unroll
    for (int hp = 0; hp < 4; hp++)
        #pragma unroll
        for (int dd = 0; dd < 4; dd++) U2[hp][dd] = 0ull;
    float ssum = 0.f, tsum = 0.f;

    int beg = g_offsets[n], end = g_offsets[n + 1];
    bool b4 = (l & 16), b3 = (l & 8), b2 = (l & 4);
    int2 pe0 = make_int2(0, 0), pe1 = pe0;
    float4 a0 = make_float4(0.f, 0.f, 0.f, 0.f), a1 = a0;
    if (beg < end)     { pe0 = g_pe[beg];     a0 = ea4[(size_t)pe0.x * 32 + l]; }
    if (beg + 1 < end) { pe1 = g_pe[beg + 1]; a1 = ea4[(size_t)pe1.x * 32 + l]; }

    for (int i = beg; i < end; i++) {
        float4 ac = a0; float phi = __int_as_float(pe0.y);
        pe0 = pe1; a0 = a1;
        if (i + 2 < end) { pe1 = g_pe[i + 2]; a1 = ea4[(size_t)pe1.x * 32 + l]; }

        u64 ax = pk2(ac.x, ac.x), ay = pk2(ac.y, ac.y), az = pk2(ac.z, ac.z), aw = pk2(ac.w, ac.w);
        // head-pair dots over this lane's 4 dims
        u64 p0 = fma2(ax, P2[0][0], fma2(ay, P2[0][1], fma2(az, P2[0][2], mul2(aw, P2[0][3]))));
        u64 p1 = fma2(ax, P2[1][0], fma2(ay, P2[1][1], fma2(az, P2[1][2], mul2(aw, P2[1][3]))));
        u64 p2 = fma2(ax, P2[2][0], fma2(ay, P2[2][1], fma2(az, P2[2][2], mul2(aw, P2[2][3]))));
        u64 p3 = fma2(ax, P2[3][0], fma2(ay, P2[3][1], fma2(az, P2[3][2], mul2(aw, P2[3][3]))));
        // halving butterfly: lane ends with full score of head (l>>2)
        u64 t0 = b4 ? p0 : p2, t1 = b4 ? p1 : p3;
        u64 k0 = b4 ? p2 : p0, k1 = b4 ? p3 : p1;
        u64 r0 = add2(k0, __shfl_xor_sync(FULL, t0, 16));
        u64 r1 = add2(k1, __shfl_xor_sync(FULL, t1, 16));
        u64 ts = b3 ? r0 : r1, kk = b3 ? r1 : r0;
        u64 q = add2(kk, __shfl_xor_sync(FULL, ts, 8));
        float lo, hi; upk2(q, lo, hi);
        float s = (b2 ? hi : lo) + __shfl_xor_sync(FULL, b2 ? lo : hi, 4);
        s += __shfl_xor_sync(FULL, s, 2);
        s += __shfl_xor_sync(FULL, s, 1);

        float ex = __expf(s + ch);     // P,ch pre-scaled by 1/sqrt(d_k)
        float wh = ex * phi;
        ssum += ex; tsum += wh;
        u64 wp[4];
        wp[0] = pk2(__shfl_sync(FULL, wh, 0),  __shfl_sync(FULL, wh, 4));
        wp[1] = pk2(__shfl_sync(FULL, wh, 8),  __shfl_sync(FULL, wh, 12));
        wp[2] = pk2(__shfl_sync(FULL, wh, 16), __shfl_sync(FULL, wh, 20));
        wp[3] = pk2(__shfl_sync(FULL, wh, 24), __shfl_sync(FULL, wh, 28));
        #pragma unroll
        for (int hp = 0; hp < 4; hp++) {
            U2[hp][0] = fma2(wp[hp], ax, U2[hp][0]);
            U2[hp][1] = fma2(wp[hp], ay, U2[hp][1]);
            U2[hp][2] = fma2(wp[hp], az, U2[hp][2]);
            U2[hp][3] = fma2(wp[hp], aw, U2[hp][3]);
        }
    }

    // normalize + stage
    float inv = (ssum > 0.f) ? (1.f / ssum) : 0.f;
    if ((l & 3) == 0) sT[w][l >> 2] = tsum * inv;
    int np = w >> 1, sel = w & 1;
    #pragma unroll
    for (int hp = 0; hp < 4; hp++) {
        u64 ip = pk2(__shfl_sync(FULL, inv, hp * 8), __shfl_sync(FULL, inv, hp * 8 + 4));
        #pragma unroll
        for (int dd = 0; dd < 4; dd++) {
            float lo, hi; upk2(mul2(U2[hp][dd], ip), lo, hi);
            int d = 4 * l + dd;
            (&sUP[np][2 * hp][d].x)[sel]     = lo;
            (&sUP[np][2 * hp + 1][d].x)[sel] = hi;
        }
    }
    __syncthreads();

    // GEMM1: node_out = Unorm @ W_V + (sum alpha*phi)*b_V  (thread=column, 4 nodes)
    int c = tid & 127, g = tid >> 7, h = c >> 4;
    int nA = g * 2, nB = g * 2 + 1;
    {
        u64 bv2 = pk2(bV[c], bV[c]);
        u64 accA = mul2(pk2(sT[2 * nA][h], sT[2 * nA + 1][h]), bv2);
        u64 accB = mul2(pk2(sT[2 * nB][h], sT[2 * nB + 1][h]), bv2);
        const u64* uA = reinterpret_cast<const u64*>(&sUP[nA][h][0]);
        const u64* uB = reinterpret_cast<const u64*>(&sUP[nB][h][0]);
        #pragma unroll 4
        for (int d = 0; d < DIM; d++) {
            float wv = WV[d * DIM + c];
            u64 wv2 = pk2(wv, wv);
            accA = fma2(uA[d], wv2, accA);
            accB = fma2(uB[d], wv2, accB);
        }
        *reinterpret_cast<u64*>(&sNOP[nA][c]) = accA;
        *reinterpret_cast<u64*>(&sNOP[nB][c]) = accB;
    }
    __syncthreads();

    // GEMM2: out = node_out @ W_O + b_O
    {
        u64 oA = pk2(bO[c], bO[c]), oB = oA;
        const u64* vA = reinterpret_cast<const u64*>(&sNOP[nA][0]);
        const u64* vB = reinterpret_cast<const u64*>(&sNOP[nB][0]);
        #pragma unroll 4
        for (int d = 0; d < DIM; d++) {
            float wo = WO[d * DIM + c];
            u64 wo2 = pk2(wo, wo);
            oA = fma2(vA[d], wo2, oA);
            oB = fma2(vB[d], wo2, oB);
        }
        int base = blockIdx.x * 8;
        float x0, x1;
        upk2(oA, x0, x1);
        out[(size_t)(base + 2 * nA) * DIM + c] = x0;
        out[(size_t)(base + 2 * nA + 1) * DIM + c] = x1;
        upk2(oB, x0, x1);
        out[(size_t)(base + 2 * nB) * DIM + c] = x0;
        out[(size_t)(base + 2 * nB + 1) * DIM + c] = x1;
    }
}

extern "C" void kernel_launch(void* const* d_in, const int* in_sizes, int n_in,
                              void* d_out, int out_size) {
    const float* x    = (const float*)d_in[0];
    const int*   ei   = (const int*)  d_in[1];
    const float* ea   = (const float*)d_in[2];
    const float* elen = (const float*)d_in[3];
    const float* WQ   = (const float*)d_in[4];
    const float* bQ   = (const float*)d_in[5];
    const float* WK   = (const float*)d_in[6];
    const float* bK   = (const float*)d_in[7];
    const float* WV   = (const float*)d_in[8];
    const float* bV   = (const float*)d_in[9];
    const float* WO   = (const float*)d_in[10];
    const float* bO   = (const float*)d_in[11];
    float* out = (float*)d_out;

    k_zero<<<(N_NODES + 255) / 256, 256>>>();
    k_hist<<<(N_EDGES + 255) / 256, 256>>>(ei);
    k_scan<<<1, 1024>>>();
    k_scatter<<<(N_EDGES + 255) / 256, 256>>>(ei, elen);
    k_wkt<<<(DIM * DIM + 255) / 256, 256>>>(WK);
    k_qp<<<N_NODES, 64>>>(x, WQ, bQ, bK);
    k_edge<<<N_NODES / 8, 256>>>((const float4*)ea, WV, bV, WO, bO, out);
}

// round 5
// speedup vs baseline: 2.1525x; 2.1525x over previous
#include <cuda_runtime.h>

#define N_NODES 50000
#define N_EDGES 800000
#define DIM 128
#define KPI 0.62831853071795865f
#define FULL 0xffffffffu

// ---- scratch ----
__device__ float g_P[(size_t)N_NODES * 1024];   // [n][h][128], pre-scaled by 0.25
__device__ float g_c[N_NODES * 8];              // (q.b_K)*0.25
__device__ float g_WKT[DIM * DIM];
__device__ int   g_counts[N_NODES];
__device__ int   g_offsets[N_NODES + 1];
__device__ int   g_cursor[N_NODES];
__device__ int2  g_pe[N_EDGES];                 // (edge, phi bits) CSR order

// ---- CSR build ----
__global__ void k_zero() {
    int i = blockIdx.x * blockDim.x + threadIdx.x;
    if (i < N_NODES) g_counts[i] = 0;
}
__global__ void k_hist(const int* __restrict__ ei) {
    int e = blockIdx.x * blockDim.x + threadIdx.x;
    if (e < N_EDGES) atomicAdd(&g_counts[ei[N_EDGES + e]], 1);
}
__global__ void k_scan() {
    __shared__ int wsum[32];
    int t = threadIdx.x, lane = t & 31, wid = t >> 5;
    int carry = 0;
    for (int base = 0; base < N_NODES; base += 1024) {
        int i = base + t;
        int v = (i < N_NODES) ? g_counts[i] : 0;
        int x = v;
        #pragma unroll
        for (int o = 1; o < 32; o <<= 1) { int y = __shfl_up_sync(FULL, x, o); if (lane >= o) x += y; }
        if (lane == 31) wsum[wid] = x;
        __syncthreads();
        if (wid == 0) {
            int s = wsum[lane];
            #pragma unroll
            for (int o = 1; o < 32; o <<= 1) { int y = __shfl_up_sync(FULL, s, o); if (lane >= o) s += y; }
            wsum[lane] = s;
        }
        __syncthreads();
        int excl = x - v + (wid ? wsum[wid - 1] : 0);
        if (i < N_NODES) { g_offsets[i] = carry + excl; g_cursor[i] = carry + excl; }
        carry += wsum[31];
        __syncthreads();
    }
    if (t == 0) g_offsets[N_NODES] = carry;
}
__global__ void k_scatter(const int* __restrict__ ei, const float* __restrict__ elen) {
    int e = blockIdx.x * blockDim.x + threadIdx.x;
    if (e < N_EDGES) {
        int j = ei[N_EDGES + e];
        int pos = atomicAdd(&g_cursor[j], 1);
        float phi = fmaf(0.5f, __cosf(elen[e] * KPI), 0.5f);
        g_pe[pos] = make_int2(e, __float_as_int(phi));
    }
}
__global__ void k_wkt(const float* __restrict__ WK) {
    int i = blockIdx.x * blockDim.x + threadIdx.x;
    if (i < DIM * DIM) g_WKT[(i % DIM) * DIM + (i / DIM)] = WK[i];
}

// ---- node precompute, 4 nodes/block: weights stream once per 4 nodes ----
__global__ void __launch_bounds__(128) k_qp(
    const float* __restrict__ x, const float* __restrict__ WQ,
    const float* __restrict__ bQ, const float* __restrict__ bK)
{
    __shared__ float sx[4][DIM], sq[4][DIM];
    int nb = blockIdx.x * 4, t = threadIdx.x;
    #pragma unroll
    for (int i = 0; i < 4; i++) sx[i][t] = x[(size_t)(nb + i) * DIM + t];
    __syncthreads();
    float q0 = bQ[t], q1 = q0, q2 = q0, q3 = q0;
    #pragma unroll 4
    for (int s = 0; s < DIM; s++) {
        float w = WQ[s * DIM + t];
        q0 = fmaf(sx[0][s], w, q0);
        q1 = fmaf(sx[1][s], w, q1);
        q2 = fmaf(sx[2][s], w, q2);
        q3 = fmaf(sx[3][s], w, q3);
    }
    sq[0][t] = q0; sq[1][t] = q1; sq[2][t] = q2; sq[3][t] = q3;
    __syncthreads();
    #pragma unroll
    for (int h = 0; h < 8; h++) {
        float p0 = 0.f, p1 = 0.f, p2 = 0.f, p3 = 0.f;
        #pragma unroll
        for (int k = 0; k < 16; k++) {
            float w = g_WKT[(h * 16 + k) * DIM + t];
            p0 = fmaf(sq[0][h * 16 + k], w, p0);
            p1 = fmaf(sq[1][h * 16 + k], w, p1);
            p2 = fmaf(sq[2][h * 16 + k], w, p2);
            p3 = fmaf(sq[3][h * 16 + k], w, p3);
        }
        g_P[(size_t)(nb + 0) * 1024 + h * DIM + t] = 0.25f * p0;
        g_P[(size_t)(nb + 1) * 1024 + h * DIM + t] = 0.25f * p1;
        g_P[(size_t)(nb + 2) * 1024 + h * DIM + t] = 0.25f * p2;
        g_P[(size_t)(nb + 3) * 1024 + h * DIM + t] = 0.25f * p3;
    }
    if (t < 32) {
        int i = t >> 3, h = t & 7;
        float cc = 0.f;
        #pragma unroll
        for (int k = 0; k < 16; k++) cc = fmaf(sq[i][h * 16 + k], bK[h * 16 + k], cc);
        g_c[(nb + i) * 8 + h] = cc * 0.25f;
    }
}

// ---- fused edge pass (warp=node) + block-cooperative epilogue ----
__global__ void __launch_bounds__(256, 2) k_edge(
    const float4* __restrict__ ea4,
    const float* __restrict__ WV, const float* __restrict__ bV,
    const float* __restrict__ WO, const float* __restrict__ bO,
    float* __restrict__ out)
{
    __shared__ float sU[8][8][DIM];   // [node][head][dim], normalized
    __shared__ float sT[8][8];        // [node][head] = sum(alpha*phi)
    __shared__ float sno[8][DIM];     // node_out
    int tid = threadIdx.x, w = tid >> 5, l = tid & 31;
    int n = blockIdx.x * 8 + w;

    // P for this node: lane l holds dims 4l..4l+3 of all 8 heads (pre-scaled 0.25)
    float4 P4[8];
    #pragma unroll
    for (int h = 0; h < 8; h++)
        P4[h] = reinterpret_cast<const float4*>(g_P + (size_t)n * 1024 + h * DIM)[l];
    float ch = g_c[n * 8 + (l >> 2)];

    float4 U[8];
    #pragma unroll
    for (int h = 0; h < 8; h++) U[h] = make_float4(0.f, 0.f, 0.f, 0.f);
    float ssum = 0.f, tsum = 0.f;
    bool b4 = (l & 16), b3 = (l & 8), b2 = (l & 4);

    int beg = g_offsets[n], end = g_offsets[n + 1];
    int2 pe0 = make_int2(0, 0), pe1 = pe0;
    float4 a0 = make_float4(0.f, 0.f, 0.f, 0.f), a1 = a0;
    if (beg < end)     { pe0 = g_pe[beg];     a0 = ea4[(size_t)pe0.x * 32 + l]; }
    if (beg + 1 < end) { pe1 = g_pe[beg + 1]; a1 = ea4[(size_t)pe1.x * 32 + l]; }

    for (int i = beg; i < end; i++) {
        float4 ac = a0; float phi = __int_as_float(pe0.y);
        pe0 = pe1; a0 = a1;
        if (i + 2 < end) { pe1 = g_pe[i + 2]; a1 = ea4[(size_t)pe1.x * 32 + l]; }

        // partial dots: p[h] over this lane's 4 dims
        float p[8];
        #pragma unroll
        for (int h = 0; h < 8; h++)
            p[h] = fmaf(ac.x, P4[h].x, fmaf(ac.y, P4[h].y, fmaf(ac.z, P4[h].z, ac.w * P4[h].w)));

        // head-halving butterfly: lane ends with full score of head (l>>2)
        float r0, r1, r2, r3;
        {
            float t0 = b4 ? p[0] : p[4], t1 = b4 ? p[1] : p[5];
            float t2 = b4 ? p[2] : p[6], t3 = b4 ? p[3] : p[7];
            r0 = (b4 ? p[4] : p[0]) + __shfl_xor_sync(FULL, t0, 16);
            r1 = (b4 ? p[5] : p[1]) + __shfl_xor_sync(FULL, t1, 16);
            r2 = (b4 ? p[6] : p[2]) + __shfl_xor_sync(FULL, t2, 16);
            r3 = (b4 ? p[7] : p[3]) + __shfl_xor_sync(FULL, t3, 16);
        }
        float s0, s1;
        {
            float t0 = b3 ? r0 : r2, t1 = b3 ? r1 : r3;
            s0 = (b3 ? r2 : r0) + __shfl_xor_sync(FULL, t0, 8);
            s1 = (b3 ? r3 : r1) + __shfl_xor_sync(FULL, t1, 8);
        }
        float s;
        {
            float t0 = b2 ? s0 : s1;
            s = (b2 ? s1 : s0) + __shfl_xor_sync(FULL, t0, 4);
        }
        s += __shfl_xor_sync(FULL, s, 2);
        s += __shfl_xor_sync(FULL, s, 1);

        float ex = __expf(s + ch);   // P, ch pre-scaled by 1/sqrt(d_k)
        float wh = ex * phi;
        ssum += ex; tsum += wh;

        // broadcast per-head weights, accumulate U
        #pragma unroll
        for (int h = 0; h < 8; h++) {
            float whh = __shfl_sync(FULL, wh, 4 * h);
            U[h].x = fmaf(whh, ac.x, U[h].x);
            U[h].y = fmaf(whh, ac.y, U[h].y);
            U[h].z = fmaf(whh, ac.z, U[h].z);
            U[h].w = fmaf(whh, ac.w, U[h].w);
        }
    }

    // normalize + stage (lane's ssum is for head l>>2)
    float invm = (ssum > 0.f) ? (1.f / ssum) : 0.f;
    if ((l & 3) == 0) sT[w][l >> 2] = tsum * invm;
    #pragma unroll
    for (int h = 0; h < 8; h++) {
        float ivh = __shfl_sync(FULL, invm, 4 * h);
        float4 v = make_float4(U[h].x * ivh, U[h].y * ivh, U[h].z * ivh, U[h].w * ivh);
        reinterpret_cast<float4*>(&sU[w][h][0])[l] = v;
    }
    __syncthreads();

    // GEMM1: node_out[n,c] = sum_d Unorm[n,h(c),d]*WV[d,c] + sT[n,h(c)]*bV[c]
    int c = tid & 127, g = tid >> 7, h = c >> 4;
    int n0 = 4 * g, n1 = n0 + 1, n2 = n0 + 2, n3 = n0 + 3;
    {
        float bv = bV[c];
        float a0c = sT[n0][h] * bv, a1c = sT[n1][h] * bv;
        float a2c = sT[n2][h] * bv, a3c = sT[n3][h] * bv;
        const float4* u0 = reinterpret_cast<const float4*>(&sU[n0][h][0]);
        const float4* u1 = reinterpret_cast<const float4*>(&sU[n1][h][0]);
        const float4* u2 = reinterpret_cast<const float4*>(&sU[n2][h][0]);
        const float4* u3 = reinterpret_cast<const float4*>(&sU[n3][h][0]);
        #pragma unroll 8
        for (int d4 = 0; d4 < 32; d4++) {
            float w0 = WV[(4 * d4 + 0) * DIM + c];
            float w1 = WV[(4 * d4 + 1) * DIM + c];
            float w2 = WV[(4 * d4 + 2) * DIM + c];
            float w3 = WV[(4 * d4 + 3) * DIM + c];
            float4 v;
            v = u0[d4]; a0c = fmaf(v.x, w0, fmaf(v.y, w1, fmaf(v.z, w2, fmaf(v.w, w3, a0c))));
            v = u1[d4]; a1c = fmaf(v.x, w0, fmaf(v.y, w1, fmaf(v.z, w2, fmaf(v.w, w3, a1c))));
            v = u2[d4]; a2c = fmaf(v.x, w0, fmaf(v.y, w1, fmaf(v.z, w2, fmaf(v.w, w3, a2c))));
            v = u3[d4]; a3c = fmaf(v.x, w0, fmaf(v.y, w1, fmaf(v.z, w2, fmaf(v.w, w3, a3c))));
        }
        sno[n0][c] = a0c; sno[n1][c] = a1c; sno[n2][c] = a2c; sno[n3][c] = a3c;
    }
    __syncthreads();

    // GEMM2: out = node_out @ W_O + b_O
    {
        float bo = bO[c];
        float o0 = bo, o1 = bo, o2 = bo, o3 = bo;
        const float4* v0 = reinterpret_cast<const float4*>(&sno[n0][0]);
        const float4* v1 = reinterpret_cast<const float4*>(&sno[n1][0]);
        const float4* v2 = reinterpret_cast<const float4*>(&sno[n2][0]);
        const float4* v3 = reinterpret_cast<const float4*>(&sno[n3][0]);
        #pragma unroll 8
        for (int d4 = 0; d4 < 32; d4++) {
            float w0 = WO[(4 * d4 + 0) * DIM + c];
            float w1 = WO[(4 * d4 + 1) * DIM + c];
            float w2 = WO[(4 * d4 + 2) * DIM + c];
            float w3 = WO[(4 * d4 + 3) * DIM + c];
            float4 v;
            v = v0[d4]; o0 = fmaf(v.x, w0, fmaf(v.y, w1, fmaf(v.z, w2, fmaf(v.w, w3, o0))));
            v = v1[d4]; o1 = fmaf(v.x, w0, fmaf(v.y, w1, fmaf(v.z, w2, fmaf(v.w, w3, o1))));
            v = v2[d4]; o2 = fmaf(v.x, w0, fmaf(v.y, w1, fmaf(v.z, w2, fmaf(v.w, w3, o2))));
            v = v3[d4]; o3 = fmaf(v.x, w0, fmaf(v.y, w1, fmaf(v.z, w2, fmaf(v.w, w3, o3))));
        }
        size_t base = (size_t)blockIdx.x * 8;
        out[(base + n0) * DIM + c] = o0;
        out[(base + n1) * DIM + c] = o1;
        out[(base + n2) * DIM + c] = o2;
        out[(base + n3) * DIM + c] = o3;
    }
}

extern "C" void kernel_launch(void* const* d_in, const int* in_sizes, int n_in,
                              void* d_out, int out_size) {
    const float* x    = (const float*)d_in[0];
    const int*   ei   = (const int*)  d_in[1];
    const float* ea   = (const float*)d_in[2];
    const float* elen = (const float*)d_in[3];
    const float* WQ   = (const float*)d_in[4];
    const float* bQ   = (const float*)d_in[5];
    const float* WK   = (const float*)d_in[6];
    const float* bK   = (const float*)d_in[7];
    const float* WV   = (const float*)d_in[8];
    const float* bV   = (const float*)d_in[9];
    const float* WO   = (const float*)d_in[10];
    const float* bO   = (const float*)d_in[11];
    float* out = (float*)d_out;

    k_zero<<<(N_NODES + 255) / 256, 256>>>();
    k_hist<<<(N_EDGES + 255) / 256, 256>>>(ei);
    k_scan<<<1, 1024>>>();
    k_scatter<<<(N_EDGES + 255) / 256, 256>>>(ei, elen);
    k_wkt<<<(DIM * DIM + 255) / 256, 256>>>(WK);
    k_qp<<<N_NODES / 4, 128>>>(x, WQ, bQ, bK);
    k_edge<<<N_NODES / 8, 256>>>((const float4*)ea, WV, bV, WO, bO, out);
}